// round 6
// baseline (speedup 1.0000x reference)
#include <cuda_runtime.h>

#define NN 50000
#define NE 800000
#define NF 64
#define TPB 256
#define NE2 (NE / 2)                 // 400000 edge-pairs
#define NB  ((NN + TPB - 1) / TPB)   // 196 node blocks
#define HWB (NN * 16 / TPB)          // 3125 half-warp-per-node blocks (exact)
#define WAVE 1216                    // 152 SMs * 8 blocks(256thr) = one full wave
// hop iteration space: NE2 edge-pairs + NN self-edges
#define HOPIT (NE2 + NN)

// Scratch (__device__ globals; zero at load; deg re-zeroed by k6 each call).
__device__ __align__(16) float  g_deg[NN];
__device__ __align__(16) float2 g_T0[NN];   // (y0_dot, dinv)
__device__ __align__(16) float2 g_T1[NN];   // (acc, 1/deg~)
__device__ __align__(16) float2 g_T2[NN];   // (acc, 1/deg~)
__device__ __align__(16) float2 g_T3[NN];   // (acc, unused)

// K1: (a) T0[i].x = x[i,:]·W  — half-warp per node, float4 loads (blocks [0,HWB))
//     (b) degree histogram over col — single-wave grid-stride (blocks [HWB, HWB+WAVE))
__global__ void k1(const float* __restrict__ x, const float* __restrict__ W,
                   const int* __restrict__ col) {
    if (blockIdx.x < HWB) {
        __shared__ float4 sW[NF / 4];
        if (threadIdx.x < NF / 4) sW[threadIdx.x] = ((const float4*)W)[threadIdx.x];
        __syncthreads();
        int t  = blockIdx.x * TPB + threadIdx.x;
        int gw = t >> 4;                 // node (exact coverage)
        int l  = t & 15;
        float4 v = ((const float4*)(x + (size_t)gw * NF))[l];
        float4 w = sW[l];
        float s = fmaf(v.x, w.x, fmaf(v.y, w.y, fmaf(v.z, w.z, v.w * w.w)));
        #pragma unroll
        for (int o = 8; o; o >>= 1) s += __shfl_xor_sync(0xffffffffu, s, o);
        if (l == 0) g_T0[gw].x = s;
    } else {
        int tid = (blockIdx.x - HWB) * TPB + threadIdx.x;
        const int GS = WAVE * TPB;
        for (int i = tid; i < NE2; i += GS) {
            int2 c = ((const int2*)col)[i];
            atomicAdd(&g_deg[c.x], 1.0f);
            atomicAdd(&g_deg[c.y], 1.0f);
        }
    }
}

// K2: node-only scale fills + accumulator zeroing.
__global__ void k2() {
    int i = blockIdx.x * TPB + threadIdx.x;
    if (i >= NN) return;
    float d   = g_deg[i] + 1.0f;     // +1 = self-loop
    float di2 = 1.0f / d;
    g_T0[i].y = rsqrtf(d);           // D^{-1/2} applied at hop-1 gather
    g_T1[i] = make_float2(0.0f, di2);
    g_T2[i] = make_float2(0.0f, di2);
    g_T3[i].x = 0.0f;
}

// Uniform hop, single-wave grid-stride over NE2 edge-pairs + NN self-edges.
// Tout[c].x += Tin[r].x * Tin[r].y
__global__ void __launch_bounds__(TPB, 8)
hop(const float2* __restrict__ Tin, float2* __restrict__ Tout,
    const int* __restrict__ row, const int* __restrict__ col) {
    int tid = blockIdx.x * TPB + threadIdx.x;
    const int GS = WAVE * TPB;
    for (int i = tid; i < HOPIT; i += GS) {
        if (i < NE2) {
            int2 r = ((const int2*)row)[i];
            int2 c = ((const int2*)col)[i];
            float2 a0 = Tin[r.x];
            float2 a1 = Tin[r.y];
            atomicAdd(&Tout[c.x].x, a0.x * a0.y);
            atomicAdd(&Tout[c.y].x, a1.x * a1.y);
        } else {
            int n = i - NE2;                 // self edge (n, n), coalesced gather
            float2 a = Tin[n];
            atomicAdd(&Tout[n].x, a.x * a.y);
        }
    }
}

// K6: final scaling + bias; re-zero deg for the next replay.
__global__ void k6(float* __restrict__ out, const float* __restrict__ b) {
    int i = blockIdx.x * TPB + threadIdx.x;
    if (i >= NN) return;
    float d = g_deg[i] + 1.0f;
    out[i] = rsqrtf(d) * g_T3[i].x + b[0];
    g_deg[i] = 0.0f;
}

extern "C" void kernel_launch(void* const* d_in, const int* in_sizes, int n_in,
                              void* d_out, int out_size) {
    const float* x  = (const float*)d_in[0];   // [NN, NF]
    const int*   ei = (const int*)d_in[1];     // [2, NE]
    const float* W  = (const float*)d_in[2];   // [1, NF]
    const float* b  = (const float*)d_in[3];   // [1]
    float* out = (float*)d_out;                // [NN]

    const int* row = ei;        // sources
    const int* col = ei + NE;   // destinations

    float2 *T0, *T1, *T2, *T3;
    cudaGetSymbolAddress((void**)&T0, g_T0);
    cudaGetSymbolAddress((void**)&T1, g_T1);
    cudaGetSymbolAddress((void**)&T2, g_T2);
    cudaGetSymbolAddress((void**)&T3, g_T3);

    k1 <<<HWB + WAVE, TPB>>>(x, W, col);   // dot + degree histogram
    k2 <<<NB, TPB>>>();                    // scales + zero accumulators
    hop<<<WAVE, TPB>>>(T0, T1, row, col);  // t1 = A~ (D^-1/2 y0)
    hop<<<WAVE, TPB>>>(T1, T2, row, col);  // t2 = A~ (D^-1 t1)
    hop<<<WAVE, TPB>>>(T2, T3, row, col);  // t3 = A~ (D^-1 t2)
    k6 <<<NB, TPB>>>(out, b);              // out = D^-1/2 t3 + b ; deg=0
}

// round 7
// speedup vs baseline: 1.0934x; 1.0934x over previous
#include <cuda_runtime.h>

#define NN 50000
#define NE 800000
#define NF 64
#define TPB 256
#define NE2 (NE / 2)                  // 400000 edge-pairs (build: 2 edges/thread)
#define EB2 ((NE2 + TPB - 1) / TPB)   // 1563 build blocks
#define NB  ((NN + TPB - 1) / TPB)    // 196 node blocks
#define HWB (NN * 16 / TPB)           // 3125 half-warp-per-node blocks (exact)
#define MAXD 64                       // rank capacity per destination
#define QPD 4                         // lanes per destination in hop
#define HB  ((NN * QPD + TPB - 1) / TPB)  // 782 hop blocks

// Scratch (__device__ globals; zero at load; deg re-zeroed by k6 each call).
__device__ int   g_degi[NN];                      // in-degree (excl. self); rank counter
__device__ int   g_src[MAXD * NN];                // in-neighbor table, plane-major
__device__ __align__(16) float g_dot[NN];         // x·W
__device__ __align__(16) float g_z0[NN];          // dinv * dot
__device__ __align__(16) float g_z1[NN];
__device__ __align__(16) float g_z2[NN];
__device__ __align__(16) float g_z3[NN];          // raw hop-3 sum
__device__ __align__(16) float g_di2[NN];         // 1/(deg+1)

// K1: (a) dot[i] = x[i,:]·W — half-warp per node, float4 loads.
//     (b) CSR build: rank = atomicAdd(deg[c]); src[rank*NN + c] = r.
__global__ void k1(const float* __restrict__ x, const float* __restrict__ W,
                   const int* __restrict__ row, const int* __restrict__ col) {
    if (blockIdx.x < HWB) {
        __shared__ float4 sW[NF / 4];
        if (threadIdx.x < NF / 4) sW[threadIdx.x] = ((const float4*)W)[threadIdx.x];
        __syncthreads();
        int t  = blockIdx.x * TPB + threadIdx.x;
        int gw = t >> 4;
        int l  = t & 15;
        float4 v = ((const float4*)(x + (size_t)gw * NF))[l];
        float4 w = sW[l];
        float s = fmaf(v.x, w.x, fmaf(v.y, w.y, fmaf(v.z, w.z, v.w * w.w)));
        #pragma unroll
        for (int o = 8; o; o >>= 1) s += __shfl_xor_sync(0xffffffffu, s, o);
        if (l == 0) g_dot[gw] = s;
    } else {
        int i = (blockIdx.x - HWB) * TPB + threadIdx.x;
        if (i >= NE2) return;
        int2 r = ((const int2*)row)[i];
        int2 c = ((const int2*)col)[i];
        int k0 = atomicAdd(&g_degi[c.x], 1);
        int k1_ = atomicAdd(&g_degi[c.y], 1);
        if (k0  < MAXD) g_src[k0  * NN + c.x] = r.x;
        if (k1_ < MAXD) g_src[k1_ * NN + c.y] = r.y;
    }
}

// K2: node scales + first message vector z0 = dinv * dot.
__global__ void k2() {
    int i = blockIdx.x * TPB + threadIdx.x;
    if (i >= NN) return;
    float d = (float)g_degi[i] + 1.0f;     // +1 = self-loop
    g_di2[i] = 1.0f / d;
    g_z0[i]  = rsqrtf(d) * g_dot[i];
}

// Hop: atomic-free gather-reduce. 4 lanes per destination.
// zout[d] = sc[d] * ( zin[d] + sum_{k<deg[d]} zin[src[k*NN+d]] )   (sc==nullptr -> raw)
__global__ void hop(const float* __restrict__ zin, float* __restrict__ zout,
                    const float* __restrict__ sc) {
    int t = blockIdx.x * TPB + threadIdx.x;
    int d = t >> 2;
    int l = t & 3;
    if (d >= NN) return;
    int dg = g_degi[d];
    if (dg > MAXD) dg = MAXD;
    float acc = (l == 0) ? zin[d] : 0.0f;          // self edge
    for (int k = l; k < dg; k += QPD)
        acc += zin[g_src[k * NN + d]];
    acc += __shfl_xor_sync(0xffffffffu, acc, 1);
    acc += __shfl_xor_sync(0xffffffffu, acc, 2);
    if (l == 0) zout[d] = sc ? acc * sc[d] : acc;
}

// K6: out = dinv * z3 + b ; re-zero deg for the next replay.
__global__ void k6(float* __restrict__ out, const float* __restrict__ b) {
    int i = blockIdx.x * TPB + threadIdx.x;
    if (i >= NN) return;
    float d = (float)g_degi[i] + 1.0f;
    out[i] = rsqrtf(d) * g_z3[i] + b[0];
    g_degi[i] = 0;
}

extern "C" void kernel_launch(void* const* d_in, const int* in_sizes, int n_in,
                              void* d_out, int out_size) {
    const float* x  = (const float*)d_in[0];   // [NN, NF]
    const int*   ei = (const int*)d_in[1];     // [2, NE]
    const float* W  = (const float*)d_in[2];   // [1, NF]
    const float* b  = (const float*)d_in[3];   // [1]
    float* out = (float*)d_out;                // [NN]

    const int* row = ei;        // sources
    const int* col = ei + NE;   // destinations

    float *z0, *z1, *z2, *z3, *di2;
    cudaGetSymbolAddress((void**)&z0, g_z0);
    cudaGetSymbolAddress((void**)&z1, g_z1);
    cudaGetSymbolAddress((void**)&z2, g_z2);
    cudaGetSymbolAddress((void**)&z3, g_z3);
    cudaGetSymbolAddress((void**)&di2, g_di2);

    k1 <<<HWB + EB2, TPB>>>(x, W, row, col);  // dot + in-neighbor table build
    k2 <<<NB, TPB>>>();                       // scales + z0
    hop<<<HB, TPB>>>(z0, z1, di2);            // z1 = D~^-1 A~ z0
    hop<<<HB, TPB>>>(z1, z2, di2);            // z2 = D~^-1 A~ z1
    hop<<<HB, TPB>>>(z2, z3, nullptr);        // z3 = A~ z2
    k6 <<<NB, TPB>>>(out, b);                 // out = D^-1/2 z3 + b ; deg=0
}

// round 8
// speedup vs baseline: 1.1534x; 1.0548x over previous
#include <cuda_runtime.h>

#define NN 50000
#define NE 800000
#define NF 64
#define TPB 256
#define NE2 (NE / 2)                  // 400000 edge-pairs (build: 2 edges/thread)
#define EB2 ((NE2 + TPB - 1) / TPB)   // 1563 build blocks
#define NB  ((NN + TPB - 1) / TPB)    // 196 node blocks
#define HWB (NN * 16 / TPB)           // 3125 half-warp-per-node blocks (exact)
#define MAXD 64                       // rank capacity per destination
#define QPD 8                         // lanes per destination in hop
#define MAXK (MAXD / QPD)             // 8 ranks max per lane
#define HB  ((NN * QPD + TPB - 1) / TPB)  // 1563 hop blocks

// Scratch (__device__ globals; zero at load; degi re-zeroed by hop3 each call).
__device__ int   g_degi[NN];                      // in-degree (excl. self); rank counter
__device__ int   g_src[MAXD * NN];                // in-neighbor table, plane-major
__device__ __align__(16) float g_dot[NN];         // x·W
__device__ __align__(16) float g_z0[NN];          // dinv * dot
__device__ __align__(16) float g_z1[NN];
__device__ __align__(16) float g_z2[NN];
__device__ __align__(16) float g_di2[NN];         // 1/(deg+1)

// K1: (a) dot[i] = x[i,:]·W — half-warp per node, float4 loads.
//     (b) table build: rank = atomicAdd(degi[c]); src[rank*NN + c] = r.
__global__ void k1(const float* __restrict__ x, const float* __restrict__ W,
                   const int* __restrict__ row, const int* __restrict__ col) {
    if (blockIdx.x < HWB) {
        __shared__ float4 sW[NF / 4];
        if (threadIdx.x < NF / 4) sW[threadIdx.x] = ((const float4*)W)[threadIdx.x];
        __syncthreads();
        int t  = blockIdx.x * TPB + threadIdx.x;
        int gw = t >> 4;
        int l  = t & 15;
        float4 v = ((const float4*)(x + (size_t)gw * NF))[l];
        float4 w = sW[l];
        float s = fmaf(v.x, w.x, fmaf(v.y, w.y, fmaf(v.z, w.z, v.w * w.w)));
        #pragma unroll
        for (int o = 8; o; o >>= 1) s += __shfl_xor_sync(0xffffffffu, s, o);
        if (l == 0) g_dot[gw] = s;
    } else {
        int i = (blockIdx.x - HWB) * TPB + threadIdx.x;
        if (i >= NE2) return;
        int2 r = ((const int2*)row)[i];
        int2 c = ((const int2*)col)[i];
        int k0 = atomicAdd(&g_degi[c.x], 1);
        int k1_ = atomicAdd(&g_degi[c.y], 1);
        if (k0  < MAXD) g_src[k0  * NN + c.x] = r.x;
        if (k1_ < MAXD) g_src[k1_ * NN + c.y] = r.y;
    }
}

// K2: node scales + first message vector z0 = dinv * dot.
__global__ void k2() {
    int i = blockIdx.x * TPB + threadIdx.x;
    if (i >= NN) return;
    float d = (float)g_degi[i] + 1.0f;     // +1 = self-loop
    g_di2[i] = 1.0f / d;
    g_z0[i]  = rsqrtf(d) * g_dot[i];
}

// Hop: atomic-free two-phase gather-reduce, QPD lanes per destination.
//   phase 1: batch-load this lane's src indices (independent, full MLP)
//   phase 2: batch-gather zin values (independent)
// Output: sc != null : zout[d] = sc[d] * (zin[d] + sum)            (hops 1-2)
//         bptr != null: zout[d] = rsqrt(deg+1)*(zin[d]+sum) + b;
//                       g_degi[d] = 0 (fused k6, last reader)       (hop 3)
__global__ void hop(const float* __restrict__ zin, float* __restrict__ zout,
                    const float* __restrict__ sc, const float* __restrict__ bptr) {
    int t = blockIdx.x * TPB + threadIdx.x;
    int d = t >> 3;
    int l = t & 7;
    if (d >= NN) return;
    int dg = g_degi[d];
    if (dg > MAXD) dg = MAXD;

    int idx[MAXK];
    int cnt = 0;
    #pragma unroll
    for (int j = 0; j < MAXK; j++) {
        int k = l + j * QPD;
        if (k < dg) idx[cnt++] = g_src[k * NN + d];
    }
    float acc = (l == 0) ? zin[d] : 0.0f;          // self edge
    #pragma unroll
    for (int j = 0; j < MAXK; j++) {
        if (j < cnt) acc += __ldg(&zin[idx[j]]);
    }
    acc += __shfl_xor_sync(0xffffffffu, acc, 1);
    acc += __shfl_xor_sync(0xffffffffu, acc, 2);
    acc += __shfl_xor_sync(0xffffffffu, acc, 4);
    if (l == 0) {
        if (bptr) {
            zout[d] = rsqrtf((float)dg + 1.0f) * acc + bptr[0];
            g_degi[d] = 0;                         // reset for next replay
        } else {
            zout[d] = acc * sc[d];
        }
    }
}

extern "C" void kernel_launch(void* const* d_in, const int* in_sizes, int n_in,
                              void* d_out, int out_size) {
    const float* x  = (const float*)d_in[0];   // [NN, NF]
    const int*   ei = (const int*)d_in[1];     // [2, NE]
    const float* W  = (const float*)d_in[2];   // [1, NF]
    const float* b  = (const float*)d_in[3];   // [1]
    float* out = (float*)d_out;                // [NN]

    const int* row = ei;        // sources
    const int* col = ei + NE;   // destinations

    float *z0, *z1, *z2, *di2;
    cudaGetSymbolAddress((void**)&z0, g_z0);
    cudaGetSymbolAddress((void**)&z1, g_z1);
    cudaGetSymbolAddress((void**)&z2, g_z2);
    cudaGetSymbolAddress((void**)&di2, g_di2);

    k1 <<<HWB + EB2, TPB>>>(x, W, row, col);     // dot + in-neighbor table build
    k2 <<<NB, TPB>>>();                          // scales + z0
    hop<<<HB, TPB>>>(z0, z1, di2, nullptr);      // z1 = D~^-1 A~ z0
    hop<<<HB, TPB>>>(z1, z2, di2, nullptr);      // z2 = D~^-1 A~ z1
    hop<<<HB, TPB>>>(z2, out, nullptr, b);       // out = D^-1/2 A~ z2 + b ; degi=0
}